// round 12
// baseline (speedup 1.0000x reference)
#include <cuda_runtime.h>
#include <cstdint>

constexpr int Bc=4, Nn=2048, Dd=256, Hh=4;
constexpr int TJ=32, NT=Nn/TJ;

__device__ float    g_Wh  [Bc*Nn*Dd];
__device__ float    g_WhR [Bc*Nn*Dd];
__device__ float    g_esrc[Bc*Hh*Nn];
__device__ float    g_edst[Bc*Hh*Nn];
__device__ float    g_ivs [Bc*Hh*Nn];
__device__ uint32_t g_bits[Bc*64*Nn];        // [b][w=j/32][i]
__device__ float    g_alpha_s[Bc*Hh*Nn*Nn];  // fallback alpha buffer

__device__ __forceinline__ float totf(float x){
    uint32_t u; asm("cvt.rna.tf32.f32 %0, %1;" : "=r"(u) : "f"(x));
    return __uint_as_float(u);
}
__device__ __forceinline__ void mma8(float* d, float4 a, float2 b){
    asm volatile("mma.sync.aligned.m16n8k8.row.col.f32.tf32.tf32.f32 "
        "{%0,%1,%2,%3}, {%4,%5,%6,%7}, {%8,%9}, {%0,%1,%2,%3};"
        : "+f"(d[0]), "+f"(d[1]), "+f"(d[2]), "+f"(d[3])
        : "r"(__float_as_uint(a.x)), "r"(__float_as_uint(a.y)),
          "r"(__float_as_uint(a.z)), "r"(__float_as_uint(a.w)),
          "r"(__float_as_uint(b.x)), "r"(__float_as_uint(b.y)));
}
__device__ __forceinline__ void cpasync16(void* smem_p, const void* gmem){
    unsigned s = (unsigned)__cvta_generic_to_shared(smem_p);
    asm volatile("cp.async.cg.shared.global [%0], [%1], 16;" :: "r"(s), "l"(gmem));
}
#define CP_COMMIT() asm volatile("cp.async.commit_group;")
__device__ __forceinline__ void cp_wait_tail(int rem){
    if(rem>=2)      asm volatile("cp.async.wait_group 2;");
    else if(rem==1) asm volatile("cp.async.wait_group 1;");
    else            asm volatile("cp.async.wait_group 0;");
}

constexpr int AST=36, BST=72;
constexpr int ABUF=128*AST, BBUF=32*BST;
constexpr int STG = ABUF + BBUF;
constexpr int SMEM_PIPE4 = 4*STG*4;          // k1

// gat_gemm stage: B 32x72 fl + ed 32 fl + bits 64 words
constexpr int ED_OFF  = 32*72;               // 2304
constexpr int BIT_OFF = ED_OFF + 32;         // 2336
constexpr int STG2F   = BIT_OFF + 64;        // 2400 floats = 9600 B
constexpr int SMEM_K4 = 4*STG2F*4;           // 38400 B

// ---------------------------------------------------------------------------
// K1: Wh = h @ W via 3-term tf32-split HMMA (fp32-accurate).
// ---------------------------------------------------------------------------
__global__ __launch_bounds__(256,2)
void gemm_h_w(const float* __restrict__ A, const float* __restrict__ Bw){
    extern __shared__ float sm[];
    const int tid = threadIdx.x, lane = tid & 31;
    const int i0 = blockIdx.x * 128;
    const int n0 = blockIdx.y * 64;
    const int NT_K = 8;
    const int mq = (tid>>5)&3, nq = tid>>7;

    float acc[2][4][4];
#pragma unroll
    for(int mf=0;mf<2;mf++)
#pragma unroll
        for(int nf=0;nf<4;nf++)
#pragma unroll
            for(int q=0;q<4;q++) acc[mf][nf][q]=0.f;

    const int a_row = tid>>3, a_ch = tid&7;
    const int b_j   = tid>>4, b_ch = tid&15;

    auto stage = [&](int t){
        const int j0 = t*TJ;
        float* Asm = sm + (t&3)*STG;
        float* Bsm = Asm + ABUF;
#pragma unroll
        for(int k=0;k<4;k++){
            int row = a_row + k*32;
            cpasync16(Asm + row*AST + a_ch*4,
                      A + (size_t)(i0+row)*256 + j0 + a_ch*4);
        }
#pragma unroll
        for(int k=0;k<2;k++){
            int j = b_j + k*16;
            cpasync16(Bsm + j*BST + b_ch*4,
                      Bw + (size_t)(j0+j)*256 + n0 + b_ch*4);
        }
        CP_COMMIT();
    };

    stage(0); stage(1); stage(2);

    for(int t=0;t<NT_K;t++){
        cp_wait_tail(NT_K-1-t);
        __syncthreads();
        if(t+3 < NT_K) stage(t+3);
        const float* As = sm + (t&3)*STG;
        const float* Bs = As + ABUF;
#pragma unroll
        for(int kb=0;kb<4;kb++){
            float4 avb[2], avs[2];
#pragma unroll
            for(int mf=0;mf<2;mf++){
                int r = mq*32 + mf*16 + (lane>>2);
                int c = kb*8 + (lane&3);
                float4 av = make_float4(As[r*AST + c],     As[(r+8)*AST + c],
                                        As[r*AST + c + 4], As[(r+8)*AST + c + 4]);
                avb[mf] = make_float4(totf(av.x), totf(av.y), totf(av.z), totf(av.w));
                avs[mf] = make_float4(av.x-avb[mf].x, av.y-avb[mf].y,
                                      av.z-avb[mf].z, av.w-avb[mf].w);
            }
#pragma unroll
            for(int nf=0;nf<4;nf++){
                int bj = (kb*8 + (lane&3))*BST + nq*32 + nf*8 + (lane>>2);
                float2 bv = make_float2(Bs[bj], Bs[bj + 4*BST]);
                float2 bvb = make_float2(totf(bv.x), totf(bv.y));
                float2 bvs = make_float2(bv.x-bvb.x, bv.y-bvb.y);
#pragma unroll
                for(int mf=0;mf<2;mf++){
                    mma8(acc[mf][nf], avb[mf], bvb);
                    mma8(acc[mf][nf], avb[mf], bvs);
                    mma8(acc[mf][nf], avs[mf], bvb);
                }
            }
        }
    }

    const int r0 = i0 + mq*32, c0 = n0 + nq*32;
#pragma unroll
    for(int mf=0;mf<2;mf++){
        int row = r0 + mf*16 + (lane>>2);
        size_t o0 = (size_t)row*256 + c0 + (lane&3)*2;
        size_t o1 = o0 + (size_t)8*256;
#pragma unroll
        for(int nf=0;nf<4;nf++){
            float2 v0 = make_float2(acc[mf][nf][0], acc[mf][nf][1]);
            float2 v1 = make_float2(acc[mf][nf][2], acc[mf][nf][3]);
            *(float2*)(g_Wh + o0 + nf*8) = v0;
            *(float2*)(g_Wh + o1 + nf*8) = v1;
            *(float2*)(g_WhR + o0 + nf*8) = make_float2(totf(v0.x), totf(v0.y));
            *(float2*)(g_WhR + o1 + nf*8) = make_float2(totf(v1.x), totf(v1.y));
        }
    }
}

// ---------------------------------------------------------------------------
// K2: e_src/e_dst projections. One warp per (b,h,n).
// ---------------------------------------------------------------------------
__global__ __launch_bounds__(256)
void gat_attn_proj(const float* __restrict__ a_src, const float* __restrict__ a_dst){
    int r = blockIdx.x*8 + (threadIdx.x>>5);
    int lane = threadIdx.x & 31;
    int b = r>>13, h = (r>>11)&3, n = r & (Nn-1);
    const float* wp = g_Wh + ((size_t)(b*Nn+n))*Dd + h*64;
    float2 w  = *(const float2*)(wp + 2*lane);
    float2 as = *(const float2*)(a_src + h*64 + 2*lane);
    float2 ad = *(const float2*)(a_dst + h*64 + 2*lane);
    float ss = w.x*as.x + w.y*as.y;
    float sd = w.x*ad.x + w.y*ad.y;
#pragma unroll
    for(int o=16;o;o>>=1){
        ss += __shfl_xor_sync(0xffffffffu, ss, o);
        sd += __shfl_xor_sync(0xffffffffu, sd, o);
    }
    if(lane==0){ g_esrc[r]=ss; g_edst[r]=sd; }
}

// ---------------------------------------------------------------------------
// K3: alpha kernel. Block = (b, 8 rows). Also dumps bit-words + iv to gmem.
// ---------------------------------------------------------------------------
__global__ __launch_bounds__(256)
void gat_alpha(const int* __restrict__ adj, float* __restrict__ alpha_out){
    __shared__ uint8_t bits[8*512];
    __shared__ float es[32], iv[32];
    const int tid = threadIdx.x;
    const int b  = blockIdx.x >> 8;
    const int i0 = (blockIdx.x & 255) * 8;

    if(tid<32) es[tid] = g_esrc[(b*Hh + (tid>>3))*Nn + i0 + (tid&7)];
    __syncthreads();

    {
        const int i = tid>>5, g = tid&31;
        const int*   arow = adj + ((size_t)(b*Nn + i0 + i))*Nn + g*4;
        const float* edb  = g_edst + (size_t)(b*Hh)*Nn + g*4;
        float E[4] = {es[i], es[8+i], es[16+i], es[24+i]};
        float S[4] = {0.f,0.f,0.f,0.f};
#pragma unroll 4
        for(int q=0;q<16;q++){
            int4 a = *(const int4*)(arow + q*128);
            float4 dv[4];
#pragma unroll
            for(int h=0;h<4;h++)
                dv[h] = *(const float4*)(edb + (size_t)h*Nn + q*128);
            int m[4] = {a.x, a.y, a.z, a.w};
#pragma unroll
            for(int jj=0;jj<4;jj++){
                bool mm = m[jj]!=0;
#pragma unroll
                for(int h=0;h<4;h++){
                    float e = E[h] + ((const float*)&dv[h])[jj];
                    e = (e>0.f)?e:0.2f*e;
                    if(mm) S[h] += __expf(e);
                }
            }
            bits[i*512 + q*32 + g] =
                (uint8_t)((m[0]?1u:0u)|(m[1]?2u:0u)|(m[2]?4u:0u)|(m[3]?8u:0u));
        }
#pragma unroll
        for(int h=0;h<4;h++)
#pragma unroll
            for(int o=16;o;o>>=1)
                S[h] += __shfl_xor_sync(0xffffffffu, S[h], o);
        if(g==0)
#pragma unroll
            for(int h=0;h<4;h++){
                float v = (S[h]>0.f) ? (1.f/S[h]) : 0.f;
                iv[h*8+i] = v;
                g_ivs[(b*Hh+h)*Nn + i0 + i] = v;
            }
    }
    __syncthreads();

    // dump bit-words, layout [b][w][i]
#pragma unroll
    for(int k=0;k<2;k++){
        int item = tid + k*256;
        int i = item & 7, w = item >> 3;
        int base = i*512 + (w>>2)*32 + 8*(w&3);
        uint32_t u0 = *(const uint32_t*)&bits[base];
        uint32_t u1 = *(const uint32_t*)&bits[base+4];
        uint32_t x0 = u0 & 0x0F0F0F0Fu, x1 = u1 & 0x0F0F0F0Fu;
        x0 = (x0 | (x0>>4)) & 0x00FF00FFu; x0 = (x0 | (x0>>8)) & 0xFFFFu;
        x1 = (x1 | (x1>>4)) & 0x00FF00FFu; x1 = (x1 | (x1>>8)) & 0xFFFFu;
        g_bits[((size_t)b*64 + w)*Nn + i0 + i] = x0 | (x1<<16);
    }

    // pass 2: stream alpha
    const int h = tid>>6, c = tid&63;
    const float* edp = g_edst + (size_t)(b*Hh+h)*Nn;
    float* ab = alpha_out + ((size_t)((b*Hh+h)*Nn) + i0)*Nn;
    const float* esh = es + h*8;
    const float* ivh = iv + h*8;
#pragma unroll
    for(int jc=0;jc<8;jc++){
        const int j = jc*256 + c*4;
        float4 ed = *(const float4*)(edp + j);
#pragma unroll
        for(int i=0;i<8;i++){
            float E = esh[i], V = ivh[i];
            uint32_t nib = bits[i*512 + (j>>2)];
            float4 o; float e;
            e=E+ed.x; e=(e>0.f)?e:0.2f*e; o.x = (nib&1u)?__expf(e)*V:0.f;
            e=E+ed.y; e=(e>0.f)?e:0.2f*e; o.y = (nib&2u)?__expf(e)*V:0.f;
            e=E+ed.z; e=(e>0.f)?e:0.2f*e; o.z = (nib&4u)?__expf(e)*V:0.f;
            e=E+ed.w; e=(e>0.f)?e:0.2f*e; o.w = (nib&8u)?__expf(e)*V:0.f;
            *(float4*)(ab + (size_t)i*Nn + j) = o;
        }
    }
}

// ---------------------------------------------------------------------------
// K4: h_out = alpha @ WhR, alpha RECOMPUTED from bits in registers.
// grid (32 it, 16 bh), 128 thr, warp = 16-row M-quarter x N=64.
// B-only 4-stage cp.async pipeline.
// ---------------------------------------------------------------------------
__global__ __launch_bounds__(128,5)
void gat_gemm(float* __restrict__ h_out){
    extern __shared__ float sm[];
    const int tid=threadIdx.x, lane=tid&31, wid=tid>>5;
    const int it=blockIdx.x, bh=blockIdx.y, b=bh>>2, h=bh&3;
    const int i0=it*64;
    const float* wbase = g_WhR + (size_t)b*Nn*Dd + h*64;
    const float* edbase = g_edst + (size_t)bh*Nn;
    const uint32_t* bitbase = g_bits + (size_t)b*64*Nn;

    const int r_lo = wid*16 + (lane>>2);
    const float es0 = g_esrc[(size_t)bh*Nn + i0 + r_lo];
    const float es1 = g_esrc[(size_t)bh*Nn + i0 + r_lo + 8];
    const float iv0 = g_ivs [(size_t)bh*Nn + i0 + r_lo];
    const float iv1 = g_ivs [(size_t)bh*Nn + i0 + r_lo + 8];

    float acc[8][4];
#pragma unroll
    for(int nf=0;nf<8;nf++)
#pragma unroll
        for(int q=0;q<4;q++) acc[nf][q]=0.f;

    auto stage=[&](int t){
        float* S = sm + (t&3)*STG2F;
        const int row = tid>>4, ch = tid&15;
#pragma unroll
        for(int k=0;k<4;k++)
            cpasync16(S + (row+k*8)*BST + ch*4,
                      wbase + (size_t)(t*32+row+k*8)*Dd + ch*4);
        if(tid<8)  cpasync16(S + ED_OFF + tid*4, edbase + t*32 + tid*4);
        if(tid<16) cpasync16(S + BIT_OFF + tid*4,
                             (const float*)(bitbase + (size_t)t*Nn + i0 + tid*4));
        CP_COMMIT();
    };

    stage(0); stage(1); stage(2);

    for(int t=0;t<NT;t++){
        cp_wait_tail(NT-1-t);
        __syncthreads();
        if(t+3 < NT) stage(t+3);
        const float* S   = sm + (t&3)*STG2F;
        const float* edt = S + ED_OFF;
        const uint32_t* bw = (const uint32_t*)(S + BIT_OFF);
        const uint32_t b0 = bw[r_lo], b1 = bw[r_lo+8];
#pragma unroll
        for(int kb=0;kb<4;kb++){
            const int c0 = kb*8 + (lane&3);
            const float ed0 = edt[c0], ed1 = edt[c0+4];
            float e, ax, ay, az, aw;
            e = es0+ed0; e=(e>0.f)?e:0.2f*e; ax = ((b0>>c0)&1u)     ? __expf(e)*iv0 : 0.f;
            e = es1+ed0; e=(e>0.f)?e:0.2f*e; ay = ((b1>>c0)&1u)     ? __expf(e)*iv1 : 0.f;
            e = es0+ed1; e=(e>0.f)?e:0.2f*e; az = ((b0>>(c0+4))&1u) ? __expf(e)*iv0 : 0.f;
            e = es1+ed1; e=(e>0.f)?e:0.2f*e; aw = ((b1>>(c0+4))&1u) ? __expf(e)*iv1 : 0.f;
            float4 av = make_float4(ax,ay,az,aw);
#pragma unroll
            for(int nf=0;nf<8;nf++){
                int bj = c0*BST + nf*8 + (lane>>2);
                float2 bv = make_float2(S[bj], S[bj + 4*BST]);
                mma8(acc[nf], av, bv);
            }
        }
    }

    const int row = i0 + r_lo;
    float* p0 = h_out + ((size_t)(b*Nn)+row)*Dd + h*64 + (lane&3)*2;
    float* p1 = p0 + (size_t)8*Dd;
#pragma unroll
    for(int nf=0;nf<8;nf++){
        *(float2*)(p0+nf*8) = make_float2(acc[nf][0],acc[nf][1]);
        *(float2*)(p1+nf*8) = make_float2(acc[nf][2],acc[nf][3]);
    }
}

// ---------------------------------------------------------------------------
extern "C" void kernel_launch(void* const* d_in, const int* in_sizes, int n_in,
                              void* d_out, int out_size){
    const float* h     = (const float*)d_in[0];
    const int*   adj   = (const int*)d_in[1];
    const float* W     = (const float*)d_in[2];
    const float* a_src = (const float*)d_in[3];
    const float* a_dst = (const float*)d_in[4];
    float* out = (float*)d_out;

    const long long houtN  = (long long)Bc*Nn*Dd;
    const long long alphaN = (long long)Bc*Hh*Nn*Nn;
    bool has_alpha = ((long long)out_size >= houtN + alphaN);
    float* alpha_buf;
    if(has_alpha){
        alpha_buf = out + houtN;
    } else {
        cudaGetSymbolAddress((void**)&alpha_buf, g_alpha_s);
    }

    cudaFuncSetAttribute(gemm_h_w, cudaFuncAttributeMaxDynamicSharedMemorySize,
                         SMEM_PIPE4);
    cudaFuncSetAttribute(gat_gemm, cudaFuncAttributeMaxDynamicSharedMemorySize,
                         SMEM_K4);

    gemm_h_w<<<dim3(64,4),256,SMEM_PIPE4>>>(h, W);
    gat_attn_proj<<<(Bc*Hh*Nn)/8,256>>>(a_src, a_dst);
    gat_alpha<<<Bc*256,256>>>(adj, alpha_buf);
    gat_gemm<<<dim3(32,16),128,SMEM_K4>>>(out);
}

// round 13
// speedup vs baseline: 1.4214x; 1.4214x over previous
#include <cuda_runtime.h>
#include <cstdint>

constexpr int Bc=4, Nn=2048, Dd=256, Hh=4;
constexpr int TJ=32, NT=Nn/TJ;

__device__ float  g_Wh  [Bc*Nn*Dd];
__device__ float  g_WhR [Bc*Nn*Dd];
__device__ float2 g_pq  [Bc*Hh*Nn];        // (exp(es), exp(.2 es)) per row
__device__ float2 g_uv  [Bc*Hh*Nn];        // (exp(ed), exp(.2 ed)) per col
__device__ float  g_alpha_s[Bc*Hh*Nn*Nn];  // fallback alpha buffer

__device__ __forceinline__ float totf(float x){
    uint32_t u; asm("cvt.rna.tf32.f32 %0, %1;" : "=r"(u) : "f"(x));
    return __uint_as_float(u);
}
__device__ __forceinline__ void mma8(float* d, float4 a, float2 b){
    asm volatile("mma.sync.aligned.m16n8k8.row.col.f32.tf32.tf32.f32 "
        "{%0,%1,%2,%3}, {%4,%5,%6,%7}, {%8,%9}, {%0,%1,%2,%3};"
        : "+f"(d[0]), "+f"(d[1]), "+f"(d[2]), "+f"(d[3])
        : "r"(__float_as_uint(a.x)), "r"(__float_as_uint(a.y)),
          "r"(__float_as_uint(a.z)), "r"(__float_as_uint(a.w)),
          "r"(__float_as_uint(b.x)), "r"(__float_as_uint(b.y)));
}
__device__ __forceinline__ void cpasync16(void* smem_p, const void* gmem){
    unsigned s = (unsigned)__cvta_generic_to_shared(smem_p);
    asm volatile("cp.async.cg.shared.global [%0], [%1], 16;" :: "r"(s), "l"(gmem));
}
#define CP_COMMIT() asm volatile("cp.async.commit_group;")
__device__ __forceinline__ void cp_wait_tail(int rem){
    if(rem>=2)      asm volatile("cp.async.wait_group 2;");
    else if(rem==1) asm volatile("cp.async.wait_group 1;");
    else            asm volatile("cp.async.wait_group 0;");
}

constexpr int AST=36, BST=72;
constexpr int ABUF=128*AST, BBUF=32*BST;
constexpr int STG = ABUF + BBUF;             // 6912 floats
constexpr int SMEM_PIPE4 = 4*STG*4;          // 110592 B

// ---------------------------------------------------------------------------
// K1: Wh = h @ W via 3-term tf32-split HMMA (fp32-accurate).
// ---------------------------------------------------------------------------
__global__ __launch_bounds__(256,2)
void gemm_h_w(const float* __restrict__ A, const float* __restrict__ Bw){
    extern __shared__ float sm[];
    const int tid = threadIdx.x, lane = tid & 31;
    const int i0 = blockIdx.x * 128;
    const int n0 = blockIdx.y * 64;
    const int NT_K = 8;
    const int mq = (tid>>5)&3, nq = tid>>7;

    float acc[2][4][4];
#pragma unroll
    for(int mf=0;mf<2;mf++)
#pragma unroll
        for(int nf=0;nf<4;nf++)
#pragma unroll
            for(int q=0;q<4;q++) acc[mf][nf][q]=0.f;

    const int a_row = tid>>3, a_ch = tid&7;
    const int b_j   = tid>>4, b_ch = tid&15;

    auto stage = [&](int t){
        const int j0 = t*TJ;
        float* Asm = sm + (t&3)*STG;
        float* Bsm = Asm + ABUF;
#pragma unroll
        for(int k=0;k<4;k++){
            int row = a_row + k*32;
            cpasync16(Asm + row*AST + a_ch*4,
                      A + (size_t)(i0+row)*256 + j0 + a_ch*4);
        }
#pragma unroll
        for(int k=0;k<2;k++){
            int j = b_j + k*16;
            cpasync16(Bsm + j*BST + b_ch*4,
                      Bw + (size_t)(j0+j)*256 + n0 + b_ch*4);
        }
        CP_COMMIT();
    };

    stage(0); stage(1); stage(2);

    for(int t=0;t<NT_K;t++){
        cp_wait_tail(NT_K-1-t);
        __syncthreads();
        if(t+3 < NT_K) stage(t+3);
        const float* As = sm + (t&3)*STG;
        const float* Bs = As + ABUF;
#pragma unroll
        for(int kb=0;kb<4;kb++){
            float4 avb[2], avs[2];
#pragma unroll
            for(int mf=0;mf<2;mf++){
                int r = mq*32 + mf*16 + (lane>>2);
                int c = kb*8 + (lane&3);
                float4 av = make_float4(As[r*AST + c],     As[(r+8)*AST + c],
                                        As[r*AST + c + 4], As[(r+8)*AST + c + 4]);
                avb[mf] = make_float4(totf(av.x), totf(av.y), totf(av.z), totf(av.w));
                avs[mf] = make_float4(av.x-avb[mf].x, av.y-avb[mf].y,
                                      av.z-avb[mf].z, av.w-avb[mf].w);
            }
#pragma unroll
            for(int nf=0;nf<4;nf++){
                int bj = (kb*8 + (lane&3))*BST + nq*32 + nf*8 + (lane>>2);
                float2 bv = make_float2(Bs[bj], Bs[bj + 4*BST]);
                float2 bvb = make_float2(totf(bv.x), totf(bv.y));
                float2 bvs = make_float2(bv.x-bvb.x, bv.y-bvb.y);
#pragma unroll
                for(int mf=0;mf<2;mf++){
                    mma8(acc[mf][nf], avb[mf], bvb);
                    mma8(acc[mf][nf], avb[mf], bvs);
                    mma8(acc[mf][nf], avs[mf], bvb);
                }
            }
        }
    }

    const int r0 = i0 + mq*32, c0 = n0 + nq*32;
#pragma unroll
    for(int mf=0;mf<2;mf++){
        int row = r0 + mf*16 + (lane>>2);
        size_t o0 = (size_t)row*256 + c0 + (lane&3)*2;
        size_t o1 = o0 + (size_t)8*256;
#pragma unroll
        for(int nf=0;nf<4;nf++){
            float2 v0 = make_float2(acc[mf][nf][0], acc[mf][nf][1]);
            float2 v1 = make_float2(acc[mf][nf][2], acc[mf][nf][3]);
            *(float2*)(g_Wh + o0 + nf*8) = v0;
            *(float2*)(g_Wh + o1 + nf*8) = v1;
            *(float2*)(g_WhR + o0 + nf*8) = make_float2(totf(v0.x), totf(v0.y));
            *(float2*)(g_WhR + o1 + nf*8) = make_float2(totf(v1.x), totf(v1.y));
        }
    }
}

// ---------------------------------------------------------------------------
// K2: projections -> factorized exponentials. One warp per (b,h,n).
// ---------------------------------------------------------------------------
__global__ __launch_bounds__(256)
void gat_attn_proj(const float* __restrict__ a_src, const float* __restrict__ a_dst){
    int r = blockIdx.x*8 + (threadIdx.x>>5);
    int lane = threadIdx.x & 31;
    int b = r>>13, h = (r>>11)&3, n = r & (Nn-1);
    const float* wp = g_Wh + ((size_t)(b*Nn+n))*Dd + h*64;
    float2 w  = *(const float2*)(wp + 2*lane);
    float2 as = *(const float2*)(a_src + h*64 + 2*lane);
    float2 ad = *(const float2*)(a_dst + h*64 + 2*lane);
    float ss = w.x*as.x + w.y*as.y;
    float sd = w.x*ad.x + w.y*ad.y;
#pragma unroll
    for(int o=16;o;o>>=1){
        ss += __shfl_xor_sync(0xffffffffu, ss, o);
        sd += __shfl_xor_sync(0xffffffffu, sd, o);
    }
    if(lane==0){
        g_pq[r] = make_float2(__expf(ss), __expf(0.2f*ss));
        g_uv[r] = make_float2(__expf(sd), __expf(0.2f*sd));
    }
}

// ---------------------------------------------------------------------------
// K3: alpha kernel, MUFU-free: alpha = bit ? max(P*u, Q*v) : 0.
// Block = (b, 8 rows), grid 1024, 256 thr.
// ---------------------------------------------------------------------------
__global__ __launch_bounds__(256)
void gat_alpha(const int* __restrict__ adj, float* __restrict__ alpha_out){
    __shared__ uint8_t bits[8*512];
    __shared__ float sp[32], sq[32], iv[32];
    const int tid = threadIdx.x;
    const int b  = blockIdx.x >> 8;
    const int i0 = (blockIdx.x & 255) * 8;

    if(tid<32){
        float2 pq = g_pq[(b*Hh + (tid>>3))*Nn + i0 + (tid&7)];
        sp[tid]=pq.x; sq[tid]=pq.y;
    }
    __syncthreads();

    // ---- pass 1: bitmask + row sums ----
    {
        const int i = tid>>5, g = tid&31;
        const int* arow = adj + ((size_t)(b*Nn + i0 + i))*Nn + g*4;
        float P[4]={sp[i],sp[8+i],sp[16+i],sp[24+i]};
        float Q[4]={sq[i],sq[8+i],sq[16+i],sq[24+i]};
        float S[4]={0.f,0.f,0.f,0.f};
#pragma unroll 2
        for(int q=0;q<16;q++){
            int4 a = *(const int4*)(arow + q*128);
            int m[4] = {a.x,a.y,a.z,a.w};
            const int j0 = g*4 + q*128;
#pragma unroll
            for(int h=0;h<4;h++){
                const float* up = (const float*)(g_uv + (size_t)(b*Hh+h)*Nn + j0);
                float4 x0 = *(const float4*)up;
                float4 x1 = *(const float4*)(up+4);
                float e0 = fmaxf(P[h]*x0.x, Q[h]*x0.y);
                float e1 = fmaxf(P[h]*x0.z, Q[h]*x0.w);
                float e2 = fmaxf(P[h]*x1.x, Q[h]*x1.y);
                float e3 = fmaxf(P[h]*x1.z, Q[h]*x1.w);
                if(m[0]) S[h]+=e0;
                if(m[1]) S[h]+=e1;
                if(m[2]) S[h]+=e2;
                if(m[3]) S[h]+=e3;
            }
            bits[i*512 + q*32 + g] =
                (uint8_t)((m[0]?1u:0u)|(m[1]?2u:0u)|(m[2]?4u:0u)|(m[3]?8u:0u));
        }
#pragma unroll
        for(int h=0;h<4;h++)
#pragma unroll
            for(int o=16;o;o>>=1)
                S[h] += __shfl_xor_sync(0xffffffffu, S[h], o);
        if(g==0)
#pragma unroll
            for(int h=0;h<4;h++)
                iv[h*8+i] = (S[h]>0.f) ? (1.f/S[h]) : 0.f;
    }
    __syncthreads();

    // ---- pass 2: stream alpha ----
    const int h = tid>>6, c = tid&63;
    const float* uvh = (const float*)(g_uv + (size_t)(b*Hh+h)*Nn);
    float* ab = alpha_out + ((size_t)((b*Hh+h)*Nn) + i0)*Nn;
    float PP[8], QQ[8];
#pragma unroll
    for(int i=0;i<8;i++){
        PP[i] = sp[h*8+i]*iv[h*8+i];
        QQ[i] = sq[h*8+i]*iv[h*8+i];
    }
#pragma unroll
    for(int jc=0;jc<8;jc++){
        const int j = jc*256 + c*4;
        float4 x0 = *(const float4*)(uvh + 2*j);
        float4 x1 = *(const float4*)(uvh + 2*j + 4);
#pragma unroll
        for(int i=0;i<8;i++){
            uint32_t nib = bits[i*512 + (j>>2)];
            float4 o;
            o.x = (nib&1u) ? fmaxf(PP[i]*x0.x, QQ[i]*x0.y) : 0.f;
            o.y = (nib&2u) ? fmaxf(PP[i]*x0.z, QQ[i]*x0.w) : 0.f;
            o.z = (nib&4u) ? fmaxf(PP[i]*x1.x, QQ[i]*x1.y) : 0.f;
            o.w = (nib&8u) ? fmaxf(PP[i]*x1.z, QQ[i]*x1.w) : 0.f;
            *(float4*)(ab + (size_t)i*Nn + j) = o;
        }
    }
}

// ---------------------------------------------------------------------------
// K4: h_out = alpha @ WhR per (b,h). M=128, 4-stage cp.async (R10 version).
// ---------------------------------------------------------------------------
__global__ __launch_bounds__(256,2)
void gat_gemm(const float* __restrict__ alpha, float* __restrict__ h_out){
    extern __shared__ float sm[];

    const int tid = threadIdx.x, lane = tid & 31;
    const int bh = blockIdx.y, b = bh>>2, h = bh&3;
    const int i0 = blockIdx.x * 128;
    const float* abase = alpha + ((size_t)bh*Nn + i0)*Nn;
    const float* wbase = g_WhR + (size_t)b*Nn*Dd + h*64;

    const int mq = (tid>>5)&3, nq = tid>>7;

    float acc[2][4][4];
#pragma unroll
    for(int mf=0;mf<2;mf++)
#pragma unroll
        for(int nf=0;nf<4;nf++)
#pragma unroll
            for(int q=0;q<4;q++) acc[mf][nf][q]=0.f;

    const int a_row = tid>>3, a_ch = tid&7;
    const int b_j   = tid>>4, b_ch = tid&15;

    auto stage = [&](int t){
        const int j0 = t*TJ;
        float* Asm = sm + (t&3)*STG;
        float* Bsm = Asm + ABUF;
#pragma unroll
        for(int k=0;k<4;k++){
            int row = a_row + k*32;
            cpasync16(Asm + row*AST + a_ch*4,
                      abase + (size_t)row*Nn + j0 + a_ch*4);
        }
#pragma unroll
        for(int k=0;k<2;k++){
            int j = b_j + k*16;
            cpasync16(Bsm + j*BST + b_ch*4,
                      wbase + (size_t)(j0+j)*Dd + b_ch*4);
        }
        CP_COMMIT();
    };

    stage(0); stage(1); stage(2);

    for(int t=0;t<NT;t++){
        cp_wait_tail(NT-1-t);
        __syncthreads();
        if(t+3 < NT) stage(t+3);
        const float* As = sm + (t&3)*STG;
        const float* Bs = As + ABUF;
#pragma unroll
        for(int kb=0;kb<4;kb++){
            float4 av[2];
#pragma unroll
            for(int mf=0;mf<2;mf++){
                int r = mq*32 + mf*16 + (lane>>2);
                int c = kb*8 + (lane&3);
                av[mf] = make_float4(As[r*AST + c],     As[(r+8)*AST + c],
                                     As[r*AST + c + 4], As[(r+8)*AST + c + 4]);
            }
            float2 bv[4];
#pragma unroll
            for(int nf=0;nf<4;nf++){
                int bj = (kb*8 + (lane&3))*BST + nq*32 + nf*8 + (lane>>2);
                bv[nf] = make_float2(Bs[bj], Bs[bj + 4*BST]);
            }
#pragma unroll
            for(int mf=0;mf<2;mf++)
#pragma unroll
                for(int nf=0;nf<4;nf++)
                    mma8(acc[mf][nf], av[mf], bv[nf]);
        }
    }

    const int r0 = i0 + mq*32, c0 = h*64 + nq*32;
#pragma unroll
    for(int mf=0;mf<2;mf++){
        int row = r0 + mf*16 + (lane>>2);
        float* p0 = h_out + ((size_t)(b*Nn) + row)*Dd + c0 + (lane&3)*2;
        float* p1 = p0 + (size_t)8*Dd;
#pragma unroll
        for(int nf=0;nf<4;nf++){
            *(float2*)(p0 + nf*8) = make_float2(acc[mf][nf][0], acc[mf][nf][1]);
            *(float2*)(p1 + nf*8) = make_float2(acc[mf][nf][2], acc[mf][nf][3]);
        }
    }
}

// ---------------------------------------------------------------------------
extern "C" void kernel_launch(void* const* d_in, const int* in_sizes, int n_in,
                              void* d_out, int out_size){
    const float* h     = (const float*)d_in[0];
    const int*   adj   = (const int*)d_in[1];
    const float* W     = (const float*)d_in[2];
    const float* a_src = (const float*)d_in[3];
    const float* a_dst = (const float*)d_in[4];
    float* out = (float*)d_out;

    const long long houtN  = (long long)Bc*Nn*Dd;
    const long long alphaN = (long long)Bc*Hh*Nn*Nn;
    bool has_alpha = ((long long)out_size >= houtN + alphaN);
    float* alpha_buf;
    if(has_alpha){
        alpha_buf = out + houtN;
    } else {
        cudaGetSymbolAddress((void**)&alpha_buf, g_alpha_s);
    }

    cudaFuncSetAttribute(gemm_h_w, cudaFuncAttributeMaxDynamicSharedMemorySize,
                         SMEM_PIPE4);
    cudaFuncSetAttribute(gat_gemm, cudaFuncAttributeMaxDynamicSharedMemorySize,
                         SMEM_PIPE4);

    gemm_h_w<<<dim3(64,4),256,SMEM_PIPE4>>>(h, W);
    gat_attn_proj<<<(Bc*Hh*Nn)/8,256>>>(a_src, a_dst);
    gat_alpha<<<Bc*256,256>>>(adj, alpha_buf);
    gat_gemm<<<dim3(16,16),256,SMEM_PIPE4>>>(alpha_buf, out);
}

// round 14
// speedup vs baseline: 1.5118x; 1.0636x over previous
#include <cuda_runtime.h>
#include <cstdint>

constexpr int Bc=4, Nn=2048, Dd=256, Hh=4;
constexpr int TJ=32, NT=Nn/TJ;

__device__ float    g_Wh  [Bc*Nn*Dd];
__device__ float    g_WhR [Bc*Nn*Dd];
__device__ float2   g_pq  [Bc*Hh*Nn];        // (exp(es), exp(.2es)) per row
__device__ float2   g_uv  [Bc*Hh*Nn];        // (exp(ed), exp(.2ed)) per col
__device__ float    g_ivs [Bc*Hh*Nn];        // 1/rowsum
__device__ uint32_t g_bits[Bc*64*Nn];        // [b][w=j/32][i]
__device__ float    g_alpha_s[Bc*Hh*Nn*Nn]; // fallback alpha buffer

__device__ __forceinline__ float totf(float x){
    uint32_t u; asm("cvt.rna.tf32.f32 %0, %1;" : "=r"(u) : "f"(x));
    return __uint_as_float(u);
}
__device__ __forceinline__ void mma8(float* d, float4 a, float2 b){
    asm volatile("mma.sync.aligned.m16n8k8.row.col.f32.tf32.tf32.f32 "
        "{%0,%1,%2,%3}, {%4,%5,%6,%7}, {%8,%9}, {%0,%1,%2,%3};"
        : "+f"(d[0]), "+f"(d[1]), "+f"(d[2]), "+f"(d[3])
        : "r"(__float_as_uint(a.x)), "r"(__float_as_uint(a.y)),
          "r"(__float_as_uint(a.z)), "r"(__float_as_uint(a.w)),
          "r"(__float_as_uint(b.x)), "r"(__float_as_uint(b.y)));
}
__device__ __forceinline__ void cpasync16(void* smem_p, const void* gmem){
    unsigned s = (unsigned)__cvta_generic_to_shared(smem_p);
    asm volatile("cp.async.cg.shared.global [%0], [%1], 16;" :: "r"(s), "l"(gmem));
}
#define CP_COMMIT() asm volatile("cp.async.commit_group;")
__device__ __forceinline__ void cp_wait_tail(int rem){
    if(rem>=2)      asm volatile("cp.async.wait_group 2;");
    else if(rem==1) asm volatile("cp.async.wait_group 1;");
    else            asm volatile("cp.async.wait_group 0;");
}

constexpr int AST=36, BST=72;
constexpr int ABUF=128*AST, BBUF=32*BST;
constexpr int STG = ABUF + BBUF;
constexpr int SMEM_PIPE4 = 4*STG*4;          // k1: 110592 B

// gat_gemm stage: B 32x72 + uv 64 + bits 64  (floats)
constexpr int UV_OFF  = 32*BST;              // 2304
constexpr int BIT_OFF = UV_OFF + 64;         // 2368
constexpr int STG3F   = BIT_OFF + 64;        // 2432 floats = 9728 B
constexpr int SMEM_G  = 4*STG3F*4;           // 38912 B -> 5 CTA/SM

// ---------------------------------------------------------------------------
// K1: Wh = h @ W via 3-term tf32-split HMMA (fp32-accurate).
// ---------------------------------------------------------------------------
__global__ __launch_bounds__(256,2)
void gemm_h_w(const float* __restrict__ A, const float* __restrict__ Bw){
    extern __shared__ float sm[];
    const int tid = threadIdx.x, lane = tid & 31;
    const int i0 = blockIdx.x * 128;
    const int n0 = blockIdx.y * 64;
    const int NT_K = 8;
    const int mq = (tid>>5)&3, nq = tid>>7;

    float acc[2][4][4];
#pragma unroll
    for(int mf=0;mf<2;mf++)
#pragma unroll
        for(int nf=0;nf<4;nf++)
#pragma unroll
            for(int q=0;q<4;q++) acc[mf][nf][q]=0.f;

    const int a_row = tid>>3, a_ch = tid&7;
    const int b_j   = tid>>4, b_ch = tid&15;

    auto stage = [&](int t){
        const int j0 = t*TJ;
        float* Asm = sm + (t&3)*STG;
        float* Bsm = Asm + ABUF;
#pragma unroll
        for(int k=0;k<4;k++){
            int row = a_row + k*32;
            cpasync16(Asm + row*AST + a_ch*4,
                      A + (size_t)(i0+row)*256 + j0 + a_ch*4);
        }
#pragma unroll
        for(int k=0;k<2;k++){
            int j = b_j + k*16;
            cpasync16(Bsm + j*BST + b_ch*4,
                      Bw + (size_t)(j0+j)*256 + n0 + b_ch*4);
        }
        CP_COMMIT();
    };

    stage(0); stage(1); stage(2);

    for(int t=0;t<NT_K;t++){
        cp_wait_tail(NT_K-1-t);
        __syncthreads();
        if(t+3 < NT_K) stage(t+3);
        const float* As = sm + (t&3)*STG;
        const float* Bs = As + ABUF;
#pragma unroll
        for(int kb=0;kb<4;kb++){
            float4 avb[2], avs[2];
#pragma unroll
            for(int mf=0;mf<2;mf++){
                int r = mq*32 + mf*16 + (lane>>2);
                int c = kb*8 + (lane&3);
                float4 av = make_float4(As[r*AST + c],     As[(r+8)*AST + c],
                                        As[r*AST + c + 4], As[(r+8)*AST + c + 4]);
                avb[mf] = make_float4(totf(av.x), totf(av.y), totf(av.z), totf(av.w));
                avs[mf] = make_float4(av.x-avb[mf].x, av.y-avb[mf].y,
                                      av.z-avb[mf].z, av.w-avb[mf].w);
            }
#pragma unroll
            for(int nf=0;nf<4;nf++){
                int bj = (kb*8 + (lane&3))*BST + nq*32 + nf*8 + (lane>>2);
                float2 bv = make_float2(Bs[bj], Bs[bj + 4*BST]);
                float2 bvb = make_float2(totf(bv.x), totf(bv.y));
                float2 bvs = make_float2(bv.x-bvb.x, bv.y-bvb.y);
#pragma unroll
                for(int mf=0;mf<2;mf++){
                    mma8(acc[mf][nf], avb[mf], bvb);
                    mma8(acc[mf][nf], avb[mf], bvs);
                    mma8(acc[mf][nf], avs[mf], bvb);
                }
            }
        }
    }

    const int r0 = i0 + mq*32, c0 = n0 + nq*32;
#pragma unroll
    for(int mf=0;mf<2;mf++){
        int row = r0 + mf*16 + (lane>>2);
        size_t o0 = (size_t)row*256 + c0 + (lane&3)*2;
        size_t o1 = o0 + (size_t)8*256;
#pragma unroll
        for(int nf=0;nf<4;nf++){
            float2 v0 = make_float2(acc[mf][nf][0], acc[mf][nf][1]);
            float2 v1 = make_float2(acc[mf][nf][2], acc[mf][nf][3]);
            *(float2*)(g_Wh + o0 + nf*8) = v0;
            *(float2*)(g_Wh + o1 + nf*8) = v1;
            *(float2*)(g_WhR + o0 + nf*8) = make_float2(totf(v0.x), totf(v0.y));
            *(float2*)(g_WhR + o1 + nf*8) = make_float2(totf(v1.x), totf(v1.y));
        }
    }
}

// ---------------------------------------------------------------------------
// K2: projections -> factorized exponentials. One warp per (b,h,n).
// ---------------------------------------------------------------------------
__global__ __launch_bounds__(256)
void gat_attn_proj(const float* __restrict__ a_src, const float* __restrict__ a_dst){
    int r = blockIdx.x*8 + (threadIdx.x>>5);
    int lane = threadIdx.x & 31;
    int b = r>>13, h = (r>>11)&3, n = r & (Nn-1);
    const float* wp = g_Wh + ((size_t)(b*Nn+n))*Dd + h*64;
    float2 w  = *(const float2*)(wp + 2*lane);
    float2 as = *(const float2*)(a_src + h*64 + 2*lane);
    float2 ad = *(const float2*)(a_dst + h*64 + 2*lane);
    float ss = w.x*as.x + w.y*as.y;
    float sd = w.x*ad.x + w.y*ad.y;
#pragma unroll
    for(int o=16;o;o>>=1){
        ss += __shfl_xor_sync(0xffffffffu, ss, o);
        sd += __shfl_xor_sync(0xffffffffu, sd, o);
    }
    if(lane==0){
        g_pq[r] = make_float2(__expf(ss), __expf(0.2f*ss));
        g_uv[r] = make_float2(__expf(sd), __expf(0.2f*sd));
    }
}

// ---------------------------------------------------------------------------
// K3: alpha kernel (MUFU-free). Also dumps bit-words + iv to gmem.
// ---------------------------------------------------------------------------
__global__ __launch_bounds__(256)
void gat_alpha(const int* __restrict__ adj, float* __restrict__ alpha_out){
    __shared__ uint8_t bits[8*512];
    __shared__ float sp[32], sq[32], iv[32];
    const int tid = threadIdx.x;
    const int b  = blockIdx.x >> 8;
    const int i0 = (blockIdx.x & 255) * 8;

    if(tid<32){
        float2 pq = g_pq[(b*Hh + (tid>>3))*Nn + i0 + (tid&7)];
        sp[tid]=pq.x; sq[tid]=pq.y;
    }
    __syncthreads();

    {
        const int i = tid>>5, g = tid&31;
        const int* arow = adj + ((size_t)(b*Nn + i0 + i))*Nn + g*4;
        float P[4]={sp[i],sp[8+i],sp[16+i],sp[24+i]};
        float Q[4]={sq[i],sq[8+i],sq[16+i],sq[24+i]};
        float S[4]={0.f,0.f,0.f,0.f};
#pragma unroll 2
        for(int q=0;q<16;q++){
            int4 a = *(const int4*)(arow + q*128);
            int m[4] = {a.x,a.y,a.z,a.w};
            const int j0 = g*4 + q*128;
#pragma unroll
            for(int h=0;h<4;h++){
                const float* up = (const float*)(g_uv + (size_t)(b*Hh+h)*Nn + j0);
                float4 x0 = *(const float4*)up;
                float4 x1 = *(const float4*)(up+4);
                float e0 = fmaxf(P[h]*x0.x, Q[h]*x0.y);
                float e1 = fmaxf(P[h]*x0.z, Q[h]*x0.w);
                float e2 = fmaxf(P[h]*x1.x, Q[h]*x1.y);
                float e3 = fmaxf(P[h]*x1.z, Q[h]*x1.w);
                if(m[0]) S[h]+=e0;
                if(m[1]) S[h]+=e1;
                if(m[2]) S[h]+=e2;
                if(m[3]) S[h]+=e3;
            }
            bits[i*512 + q*32 + g] =
                (uint8_t)((m[0]?1u:0u)|(m[1]?2u:0u)|(m[2]?4u:0u)|(m[3]?8u:0u));
        }
#pragma unroll
        for(int h=0;h<4;h++)
#pragma unroll
            for(int o=16;o;o>>=1)
                S[h] += __shfl_xor_sync(0xffffffffu, S[h], o);
        if(g==0)
#pragma unroll
            for(int h=0;h<4;h++){
                float v = (S[h]>0.f) ? (1.f/S[h]) : 0.f;
                iv[h*8+i] = v;
                g_ivs[(b*Hh+h)*Nn + i0 + i] = v;
            }
    }
    __syncthreads();

    // dump bit-words, layout [b][w][i]
#pragma unroll
    for(int k=0;k<2;k++){
        int item = tid + k*256;
        int i = item & 7, w = item >> 3;
        int base = i*512 + (w>>2)*32 + 8*(w&3);
        uint32_t u0 = *(const uint32_t*)&bits[base];
        uint32_t u1 = *(const uint32_t*)&bits[base+4];
        uint32_t x0 = u0 & 0x0F0F0F0Fu, x1 = u1 & 0x0F0F0F0Fu;
        x0 = (x0 | (x0>>4)) & 0x00FF00FFu; x0 = (x0 | (x0>>8)) & 0xFFFFu;
        x1 = (x1 | (x1>>4)) & 0x00FF00FFu; x1 = (x1 | (x1>>8)) & 0xFFFFu;
        g_bits[((size_t)b*64 + w)*Nn + i0 + i] = x0 | (x1<<16);
    }

    // pass 2: stream alpha
    const int h = tid>>6, c = tid&63;
    const float* uvh = (const float*)(g_uv + (size_t)(b*Hh+h)*Nn);
    float* ab = alpha_out + ((size_t)((b*Hh+h)*Nn) + i0)*Nn;
    float PP[8], QQ[8];
#pragma unroll
    for(int i=0;i<8;i++){
        PP[i] = sp[h*8+i]*iv[h*8+i];
        QQ[i] = sq[h*8+i]*iv[h*8+i];
    }
#pragma unroll
    for(int jc=0;jc<8;jc++){
        const int j = jc*256 + c*4;
        float4 x0 = *(const float4*)(uvh + 2*j);
        float4 x1 = *(const float4*)(uvh + 2*j + 4);
#pragma unroll
        for(int i=0;i<8;i++){
            uint32_t nib = bits[i*512 + (j>>2)];
            float4 o;
            o.x = (nib&1u) ? fmaxf(PP[i]*x0.x, QQ[i]*x0.y) : 0.f;
            o.y = (nib&2u) ? fmaxf(PP[i]*x0.z, QQ[i]*x0.w) : 0.f;
            o.z = (nib&4u) ? fmaxf(PP[i]*x1.x, QQ[i]*x1.y) : 0.f;
            o.w = (nib&8u) ? fmaxf(PP[i]*x1.z, QQ[i]*x1.w) : 0.f;
            *(float4*)(ab + (size_t)i*Nn + j) = o;
        }
    }
}

// ---------------------------------------------------------------------------
// K4: h_out = alpha @ WhR with alpha recomputed from bits (MUFU-free).
// grid (32 it, 16 bh), 128 thr, warp = 16 rows x N=64. B+uv+bits 4-stage pipe.
// ---------------------------------------------------------------------------
__global__ __launch_bounds__(128,5)
void gat_gemm(float* __restrict__ h_out){
    extern __shared__ float sm[];
    const int tid=threadIdx.x, lane=tid&31, wid=tid>>5;
    const int it=blockIdx.x, bh=blockIdx.y, b=bh>>2, h=bh&3;
    const int i0=it*64;
    const float* wbase = g_WhR + (size_t)b*Nn*Dd + h*64;
    const float* uvbase = (const float*)(g_uv + (size_t)bh*Nn);
    const uint32_t* bitbase = g_bits + (size_t)b*64*Nn;

    const int r_lo = wid*16 + (lane>>2);
    const int gi = i0 + r_lo;
    float2 pq0 = g_pq[(size_t)bh*Nn + gi];
    float2 pq1 = g_pq[(size_t)bh*Nn + gi + 8];
    const float iv0 = g_ivs[(size_t)bh*Nn + gi];
    const float iv1 = g_ivs[(size_t)bh*Nn + gi + 8];
    const float P0 = pq0.x*iv0, Q0 = pq0.y*iv0;
    const float P1 = pq1.x*iv1, Q1 = pq1.y*iv1;

    float acc[8][4];
#pragma unroll
    for(int nf=0;nf<8;nf++)
#pragma unroll
        for(int q=0;q<4;q++) acc[nf][q]=0.f;

    auto stage=[&](int t){
        float* S = sm + (t&3)*STG3F;
        const int row = tid>>4, ch = tid&15;
#pragma unroll
        for(int k=0;k<4;k++)
            cpasync16(S + (row+k*8)*BST + ch*4,
                      wbase + (size_t)(t*32+row+k*8)*Dd + ch*4);
        if(tid<16) cpasync16(S + UV_OFF + tid*4, uvbase + t*64 + tid*4);
        else if(tid<32) cpasync16(S + BIT_OFF + (tid-16)*4,
                         (const float*)(bitbase + (size_t)t*Nn + i0) + (tid-16)*4);
        CP_COMMIT();
    };

    stage(0); stage(1); stage(2);

    for(int t=0;t<NT;t++){
        cp_wait_tail(NT-1-t);
        __syncthreads();
        if(t+3 < NT) stage(t+3);
        const float* S = sm + (t&3)*STG3F;
        const float2* uvt = (const float2*)(S + UV_OFF);
        const uint32_t* bw = (const uint32_t*)(S + BIT_OFF);
        const uint32_t b0 = bw[r_lo], b1 = bw[r_lo+8];
#pragma unroll
        for(int kb=0;kb<4;kb++){
            const int c0 = kb*8 + (lane&3);
            float2 x0 = uvt[c0];
            float2 x1 = uvt[c0+4];
            float ax = ((b0>>c0)&1u)     ? fmaxf(P0*x0.x, Q0*x0.y) : 0.f;
            float ay = ((b1>>c0)&1u)     ? fmaxf(P1*x0.x, Q1*x0.y) : 0.f;
            float az = ((b0>>(c0+4))&1u) ? fmaxf(P0*x1.x, Q0*x1.y) : 0.f;
            float aw = ((b1>>(c0+4))&1u) ? fmaxf(P1*x1.x, Q1*x1.y) : 0.f;
            float4 av = make_float4(ax,ay,az,aw);
#pragma unroll
            for(int nf=0;nf<8;nf++){
                int bj = c0*BST + nf*8 + (lane>>2);
                float2 bv = make_float2(S[bj], S[bj + 4*BST]);
                mma8(acc[nf], av, bv);
            }
        }
    }

    const int row = i0 + r_lo;
    float* p0 = h_out + ((size_t)(b*Nn)+row)*Dd + h*64 + (lane&3)*2;
    float* p1 = p0 + (size_t)8*Dd;
#pragma unroll
    for(int nf=0;nf<8;nf++){
        *(float2*)(p0+nf*8) = make_float2(acc[nf][0],acc[nf][1]);
        *(float2*)(p1+nf*8) = make_float2(acc[nf][2],acc[nf][3]);
    }
}

// ---------------------------------------------------------------------------
extern "C" void kernel_launch(void* const* d_in, const int* in_sizes, int n_in,
                              void* d_out, int out_size){
    const float* h     = (const float*)d_in[0];
    const int*   adj   = (const int*)d_in[1];
    const float* W     = (const float*)d_in[2];
    const float* a_src = (const float*)d_in[3];
    const float* a_dst = (const float*)d_in[4];
    float* out = (float*)d_out;

    const long long houtN  = (long long)Bc*Nn*Dd;
    const long long alphaN = (long long)Bc*Hh*Nn*Nn;
    bool has_alpha = ((long long)out_size >= houtN + alphaN);
    float* alpha_buf;
    if(has_alpha){
        alpha_buf = out + houtN;
    } else {
        cudaGetSymbolAddress((void**)&alpha_buf, g_alpha_s);
    }

    cudaFuncSetAttribute(gemm_h_w, cudaFuncAttributeMaxDynamicSharedMemorySize,
                         SMEM_PIPE4);
    cudaFuncSetAttribute(gat_gemm, cudaFuncAttributeMaxDynamicSharedMemorySize,
                         SMEM_G);

    gemm_h_w<<<dim3(64,4),256,SMEM_PIPE4>>>(h, W);
    gat_attn_proj<<<(Bc*Hh*Nn)/8,256>>>(a_src, a_dst);
    gat_alpha<<<Bc*256,256>>>(adj, alpha_buf);
    gat_gemm<<<dim3(32,16),128,SMEM_G>>>(out);
}

// round 15
// speedup vs baseline: 1.6442x; 1.0876x over previous
#include <cuda_runtime.h>
#include <cstdint>

constexpr int Bc=4, Nn=2048, Dd=256, Hh=4;
constexpr int TJ=32, NT=Nn/TJ;

__device__ float    g_Wh  [Bc*Nn*Dd];
__device__ float    g_WhR [Bc*Nn*Dd];
__device__ float2   g_pq  [Bc*Hh*Nn];        // (exp(es), exp(.2es)) per row
__device__ float2   g_uv  [Bc*Hh*Nn];        // (exp(ed), exp(.2ed)) per col
__device__ float    g_ivs [Bc*Hh*Nn];        // 1/rowsum
__device__ uint32_t g_bits[Bc*64*Nn];        // [b][w=j/32][i], bit c = col w*32+c
__device__ float    g_alpha_s[Bc*Hh*Nn*Nn]; // fallback alpha buffer

__device__ __forceinline__ float totf(float x){
    uint32_t u; asm("cvt.rna.tf32.f32 %0, %1;" : "=r"(u) : "f"(x));
    return __uint_as_float(u);
}
__device__ __forceinline__ void mma8(float* d, float4 a, float2 b){
    asm volatile("mma.sync.aligned.m16n8k8.row.col.f32.tf32.tf32.f32 "
        "{%0,%1,%2,%3}, {%4,%5,%6,%7}, {%8,%9}, {%0,%1,%2,%3};"
        : "+f"(d[0]), "+f"(d[1]), "+f"(d[2]), "+f"(d[3])
        : "r"(__float_as_uint(a.x)), "r"(__float_as_uint(a.y)),
          "r"(__float_as_uint(a.z)), "r"(__float_as_uint(a.w)),
          "r"(__float_as_uint(b.x)), "r"(__float_as_uint(b.y)));
}
__device__ __forceinline__ void cpasync16(void* smem_p, const void* gmem){
    unsigned s = (unsigned)__cvta_generic_to_shared(smem_p);
    asm volatile("cp.async.cg.shared.global [%0], [%1], 16;" :: "r"(s), "l"(gmem));
}
#define CP_COMMIT() asm volatile("cp.async.commit_group;")
__device__ __forceinline__ void cp_wait_tail(int rem){
    if(rem>=2)      asm volatile("cp.async.wait_group 2;");
    else if(rem==1) asm volatile("cp.async.wait_group 1;");
    else            asm volatile("cp.async.wait_group 0;");
}

constexpr int AST=36, BST=72;
constexpr int ABUF=128*AST, BBUF=32*BST;
constexpr int STG = ABUF + BBUF;
constexpr int SMEM_PIPE4 = 4*STG*4;          // k1: 110592 B

// fused-kernel gemm stage: B 32x72 + uv 64 + bits 64 (floats)
constexpr int UV_OFF  = 32*BST;              // 2304
constexpr int BIT_OFF = UV_OFF + 64;         // 2368
constexpr int STG3F   = BIT_OFF + 64;        // 2432 floats = 9728 B
constexpr int SMEM_G  = 4*STG3F*4;           // 38912 B -> 5 CTA/SM

// ---------------------------------------------------------------------------
// K1: Wh = h @ W via 3-term tf32-split HMMA (fp32-accurate).
// ---------------------------------------------------------------------------
__global__ __launch_bounds__(256,2)
void gemm_h_w(const float* __restrict__ A, const float* __restrict__ Bw){
    extern __shared__ float sm[];
    const int tid = threadIdx.x, lane = tid & 31;
    const int i0 = blockIdx.x * 128;
    const int n0 = blockIdx.y * 64;
    const int NT_K = 8;
    const int mq = (tid>>5)&3, nq = tid>>7;

    float acc[2][4][4];
#pragma unroll
    for(int mf=0;mf<2;mf++)
#pragma unroll
        for(int nf=0;nf<4;nf++)
#pragma unroll
            for(int q=0;q<4;q++) acc[mf][nf][q]=0.f;

    const int a_row = tid>>3, a_ch = tid&7;
    const int b_j   = tid>>4, b_ch = tid&15;

    auto stage = [&](int t){
        const int j0 = t*TJ;
        float* Asm = sm + (t&3)*STG;
        float* Bsm = Asm + ABUF;
#pragma unroll
        for(int k=0;k<4;k++){
            int row = a_row + k*32;
            cpasync16(Asm + row*AST + a_ch*4,
                      A + (size_t)(i0+row)*256 + j0 + a_ch*4);
        }
#pragma unroll
        for(int k=0;k<2;k++){
            int j = b_j + k*16;
            cpasync16(Bsm + j*BST + b_ch*4,
                      Bw + (size_t)(j0+j)*256 + n0 + b_ch*4);
        }
        CP_COMMIT();
    };

    stage(0); stage(1); stage(2);

    for(int t=0;t<NT_K;t++){
        cp_wait_tail(NT_K-1-t);
        __syncthreads();
        if(t+3 < NT_K) stage(t+3);
        const float* As = sm + (t&3)*STG;
        const float* Bs = As + ABUF;
#pragma unroll
        for(int kb=0;kb<4;kb++){
            float4 avb[2], avs[2];
#pragma unroll
            for(int mf=0;mf<2;mf++){
                int r = mq*32 + mf*16 + (lane>>2);
                int c = kb*8 + (lane&3);
                float4 av = make_float4(As[r*AST + c],     As[(r+8)*AST + c],
                                        As[r*AST + c + 4], As[(r+8)*AST + c + 4]);
                avb[mf] = make_float4(totf(av.x), totf(av.y), totf(av.z), totf(av.w));
                avs[mf] = make_float4(av.x-avb[mf].x, av.y-avb[mf].y,
                                      av.z-avb[mf].z, av.w-avb[mf].w);
            }
#pragma unroll
            for(int nf=0;nf<4;nf++){
                int bj = (kb*8 + (lane&3))*BST + nq*32 + nf*8 + (lane>>2);
                float2 bv = make_float2(Bs[bj], Bs[bj + 4*BST]);
                float2 bvb = make_float2(totf(bv.x), totf(bv.y));
                float2 bvs = make_float2(bv.x-bvb.x, bv.y-bvb.y);
#pragma unroll
                for(int mf=0;mf<2;mf++){
                    mma8(acc[mf][nf], avb[mf], bvb);
                    mma8(acc[mf][nf], avb[mf], bvs);
                    mma8(acc[mf][nf], avs[mf], bvb);
                }
            }
        }
    }

    const int r0 = i0 + mq*32, c0 = n0 + nq*32;
#pragma unroll
    for(int mf=0;mf<2;mf++){
        int row = r0 + mf*16 + (lane>>2);
        size_t o0 = (size_t)row*256 + c0 + (lane&3)*2;
        size_t o1 = o0 + (size_t)8*256;
#pragma unroll
        for(int nf=0;nf<4;nf++){
            float2 v0 = make_float2(acc[mf][nf][0], acc[mf][nf][1]);
            float2 v1 = make_float2(acc[mf][nf][2], acc[mf][nf][3]);
            *(float2*)(g_Wh + o0 + nf*8) = v0;
            *(float2*)(g_Wh + o1 + nf*8) = v1;
            *(float2*)(g_WhR + o0 + nf*8) = make_float2(totf(v0.x), totf(v0.y));
            *(float2*)(g_WhR + o1 + nf*8) = make_float2(totf(v1.x), totf(v1.y));
        }
    }
}

// ---------------------------------------------------------------------------
// K2: projections -> factorized exponentials. One warp per (b,h,n).
// ---------------------------------------------------------------------------
__global__ __launch_bounds__(256)
void gat_attn_proj(const float* __restrict__ a_src, const float* __restrict__ a_dst){
    int r = blockIdx.x*8 + (threadIdx.x>>5);
    int lane = threadIdx.x & 31;
    int b = r>>13, h = (r>>11)&3, n = r & (Nn-1);
    const float* wp = g_Wh + ((size_t)(b*Nn+n))*Dd + h*64;
    float2 w  = *(const float2*)(wp + 2*lane);
    float2 as = *(const float2*)(a_src + h*64 + 2*lane);
    float2 ad = *(const float2*)(a_dst + h*64 + 2*lane);
    float ss = w.x*as.x + w.y*as.y;
    float sd = w.x*ad.x + w.y*ad.y;
#pragma unroll
    for(int o=16;o;o>>=1){
        ss += __shfl_xor_sync(0xffffffffu, ss, o);
        sd += __shfl_xor_sync(0xffffffffu, sd, o);
    }
    if(lane==0){
        g_pq[r] = make_float2(__expf(ss), __expf(0.2f*ss));
        g_uv[r] = make_float2(__expf(sd), __expf(0.2f*sd));
    }
}

// ---------------------------------------------------------------------------
// K3: stats only — adj -> packed bit-words + iv (MUFU-free row sums).
// ---------------------------------------------------------------------------
__global__ __launch_bounds__(256)
void gat_stats(const int* __restrict__ adj){
    __shared__ uint8_t bits[8*512];
    __shared__ float sp[32], sq[32];
    const int tid = threadIdx.x;
    const int b  = blockIdx.x >> 8;
    const int i0 = (blockIdx.x & 255) * 8;

    if(tid<32){
        float2 pq = g_pq[(b*Hh + (tid>>3))*Nn + i0 + (tid&7)];
        sp[tid]=pq.x; sq[tid]=pq.y;
    }
    __syncthreads();

    {
        const int i = tid>>5, g = tid&31;
        const int* arow = adj + ((size_t)(b*Nn + i0 + i))*Nn + g*4;
        float P[4]={sp[i],sp[8+i],sp[16+i],sp[24+i]};
        float Q[4]={sq[i],sq[8+i],sq[16+i],sq[24+i]};
        float S[4]={0.f,0.f,0.f,0.f};
#pragma unroll 2
        for(int q=0;q<16;q++){
            int4 a = *(const int4*)(arow + q*128);
            int m[4] = {a.x,a.y,a.z,a.w};
            const int j0 = g*4 + q*128;
#pragma unroll
            for(int h=0;h<4;h++){
                const float* up = (const float*)(g_uv + (size_t)(b*Hh+h)*Nn + j0);
                float4 x0 = *(const float4*)up;
                float4 x1 = *(const float4*)(up+4);
                float e0 = fmaxf(P[h]*x0.x, Q[h]*x0.y);
                float e1 = fmaxf(P[h]*x0.z, Q[h]*x0.w);
                float e2 = fmaxf(P[h]*x1.x, Q[h]*x1.y);
                float e3 = fmaxf(P[h]*x1.z, Q[h]*x1.w);
                if(m[0]) S[h]+=e0;
                if(m[1]) S[h]+=e1;
                if(m[2]) S[h]+=e2;
                if(m[3]) S[h]+=e3;
            }
            bits[i*512 + q*32 + g] =
                (uint8_t)((m[0]?1u:0u)|(m[1]?2u:0u)|(m[2]?4u:0u)|(m[3]?8u:0u));
        }
#pragma unroll
        for(int h=0;h<4;h++)
#pragma unroll
            for(int o=16;o;o>>=1)
                S[h] += __shfl_xor_sync(0xffffffffu, S[h], o);
        if(g==0)
#pragma unroll
            for(int h=0;h<4;h++)
                g_ivs[(b*Hh+h)*Nn + i0 + i] = (S[h]>0.f) ? (1.f/S[h]) : 0.f;
    }
    __syncthreads();

    // dump packed bit-words, layout [b][w][i]
#pragma unroll
    for(int k=0;k<2;k++){
        int item = tid + k*256;
        int i = item & 7, w = item >> 3;
        int base = i*512 + w*8;
        uint32_t u0 = *(const uint32_t*)&bits[base];
        uint32_t u1 = *(const uint32_t*)&bits[base+4];
        uint32_t x0 = u0 & 0x0F0F0F0Fu, x1 = u1 & 0x0F0F0F0Fu;
        x0 = (x0 | (x0>>4)) & 0x00FF00FFu; x0 = (x0 | (x0>>8)) & 0xFFFFu;
        x1 = (x1 | (x1>>4)) & 0x00FF00FFu; x1 = (x1 | (x1>>8)) & 0xFFFFu;
        g_bits[((size_t)b*64 + w)*Nn + i0 + i] = x0 | (x1<<16);
    }
}

// ---------------------------------------------------------------------------
// K4 (fused): bid<512 -> GEMM block (recompute alpha from bits, HMMA);
//             bid>=512 -> alpha writer block (DRAM-bound, overlaps GEMM).
// ---------------------------------------------------------------------------
__global__ __launch_bounds__(128,5)
void gat_fused(float* __restrict__ h_out, float* __restrict__ alpha_out){
    extern __shared__ float sm[];
    const int tid=threadIdx.x, lane=tid&31, wid=tid>>5;
    const int bid = blockIdx.x;

    if(bid < 512){
        // ================= GEMM path (R14-verified) =================
        const int it=bid&31, bh=bid>>5, b=bh>>2, h=bh&3;
        const int i0=it*64;
        const float* wbase = g_WhR + (size_t)b*Nn*Dd + h*64;
        const float* uvbase = (const float*)(g_uv + (size_t)bh*Nn);
        const uint32_t* bitbase = g_bits + (size_t)b*64*Nn;

        const int r_lo = wid*16 + (lane>>2);
        const int gi = i0 + r_lo;
        float2 pq0 = g_pq[(size_t)bh*Nn + gi];
        float2 pq1 = g_pq[(size_t)bh*Nn + gi + 8];
        const float iv0 = g_ivs[(size_t)bh*Nn + gi];
        const float iv1 = g_ivs[(size_t)bh*Nn + gi + 8];
        const float P0 = pq0.x*iv0, Q0 = pq0.y*iv0;
        const float P1 = pq1.x*iv1, Q1 = pq1.y*iv1;

        float acc[8][4];
#pragma unroll
        for(int nf=0;nf<8;nf++)
#pragma unroll
            for(int q=0;q<4;q++) acc[nf][q]=0.f;

        auto stage=[&](int t){
            float* S = sm + (t&3)*STG3F;
            const int row = tid>>4, ch = tid&15;
#pragma unroll
            for(int k=0;k<4;k++)
                cpasync16(S + (row+k*8)*BST + ch*4,
                          wbase + (size_t)(t*32+row+k*8)*Dd + ch*4);
            if(tid<16) cpasync16(S + UV_OFF + tid*4, uvbase + t*64 + tid*4);
            else if(tid<32) cpasync16(S + BIT_OFF + (tid-16)*4,
                             (const float*)(bitbase + (size_t)t*Nn + i0) + (tid-16)*4);
            CP_COMMIT();
        };

        stage(0); stage(1); stage(2);

        for(int t=0;t<NT;t++){
            cp_wait_tail(NT-1-t);
            __syncthreads();
            if(t+3 < NT) stage(t+3);
            const float* S = sm + (t&3)*STG3F;
            const float2* uvt = (const float2*)(S + UV_OFF);
            const uint32_t* bw = (const uint32_t*)(S + BIT_OFF);
            const uint32_t b0 = bw[r_lo], b1 = bw[r_lo+8];
#pragma unroll
            for(int kb=0;kb<4;kb++){
                const int c0 = kb*8 + (lane&3);
                float2 x0 = uvt[c0];
                float2 x1 = uvt[c0+4];
                float ax = ((b0>>c0)&1u)     ? fmaxf(P0*x0.x, Q0*x0.y) : 0.f;
                float ay = ((b1>>c0)&1u)     ? fmaxf(P1*x0.x, Q1*x0.y) : 0.f;
                float az = ((b0>>(c0+4))&1u) ? fmaxf(P0*x1.x, Q0*x1.y) : 0.f;
                float aw = ((b1>>(c0+4))&1u) ? fmaxf(P1*x1.x, Q1*x1.y) : 0.f;
                float4 av = make_float4(ax,ay,az,aw);
#pragma unroll
                for(int nf=0;nf<8;nf++){
                    int bj = c0*BST + nf*8 + (lane>>2);
                    float2 bv = make_float2(S[bj], S[bj + 4*BST]);
                    mma8(acc[nf], av, bv);
                }
            }
        }

        const int row = i0 + r_lo;
        float* p0 = h_out + ((size_t)(b*Nn)+row)*Dd + h*64 + (lane&3)*2;
        float* p1 = p0 + (size_t)8*Dd;
#pragma unroll
        for(int nf=0;nf<8;nf++){
            *(float2*)(p0+nf*8) = make_float2(acc[nf][0],acc[nf][1]);
            *(float2*)(p1+nf*8) = make_float2(acc[nf][2],acc[nf][3]);
        }
    } else {
        // ================= alpha writer path =================
        const int wb = bid - 512;
        const int b  = wb >> 8;
        const int i0 = (wb & 255) * 8;
        float* sp  = sm;          // [32]
        float* sq  = sm + 32;
        float* siv = sm + 64;
        uint32_t* sbw = (uint32_t*)(sm + 96);   // [i][w] 512 words

        if(tid<32){
            int g = (b*Hh + (tid>>3))*Nn + i0 + (tid&7);
            float2 pq = g_pq[g];
            sp[tid]=pq.x; sq[tid]=pq.y; siv[tid]=g_ivs[g];
        }
#pragma unroll
        for(int k=0;k<4;k++){
            int item = tid + k*128;
            int w = item>>3, i = item&7;
            sbw[i*64+w] = g_bits[((size_t)b*64 + w)*Nn + i0 + i];
        }
        __syncthreads();

        const int h = tid>>5, c = tid&31;
        const float* uvh = (const float*)(g_uv + (size_t)(b*Hh+h)*Nn);
        float* ab = alpha_out + ((size_t)((b*Hh+h)*Nn) + i0)*Nn;
        float PP[8], QQ[8];
#pragma unroll
        for(int i=0;i<8;i++){
            PP[i] = sp[h*8+i]*siv[h*8+i];
            QQ[i] = sq[h*8+i]*siv[h*8+i];
        }
#pragma unroll 2
        for(int jc=0;jc<16;jc++){
            const int j = jc*128 + c*4;
            float4 x0 = *(const float4*)(uvh + 2*j);
            float4 x1 = *(const float4*)(uvh + 2*j + 4);
            const int w  = j>>5;
            const int sh = ((j>>2)&7)*4;
#pragma unroll
            for(int i=0;i<8;i++){
                uint32_t nib = sbw[i*64+w] >> sh;
                float4 o;
                o.x = (nib&1u) ? fmaxf(PP[i]*x0.x, QQ[i]*x0.y) : 0.f;
                o.y = (nib&2u) ? fmaxf(PP[i]*x0.z, QQ[i]*x0.w) : 0.f;
                o.z = (nib&4u) ? fmaxf(PP[i]*x1.x, QQ[i]*x1.y) : 0.f;
                o.w = (nib&8u) ? fmaxf(PP[i]*x1.z, QQ[i]*x1.w) : 0.f;
                *(float4*)(ab + (size_t)i*Nn + j) = o;
            }
        }
    }
}

// ---------------------------------------------------------------------------
extern "C" void kernel_launch(void* const* d_in, const int* in_sizes, int n_in,
                              void* d_out, int out_size){
    const float* h     = (const float*)d_in[0];
    const int*   adj   = (const int*)d_in[1];
    const float* W     = (const float*)d_in[2];
    const float* a_src = (const float*)d_in[3];
    const float* a_dst = (const float*)d_in[4];
    float* out = (float*)d_out;

    const long long houtN  = (long long)Bc*Nn*Dd;
    const long long alphaN = (long long)Bc*Hh*Nn*Nn;
    bool has_alpha = ((long long)out_size >= houtN + alphaN);
    float* alpha_buf;
    if(has_alpha){
        alpha_buf = out + houtN;
    } else {
        cudaGetSymbolAddress((void**)&alpha_buf, g_alpha_s);
    }

    cudaFuncSetAttribute(gemm_h_w, cudaFuncAttributeMaxDynamicSharedMemorySize,
                         SMEM_PIPE4);
    cudaFuncSetAttribute(gat_fused, cudaFuncAttributeMaxDynamicSharedMemorySize,
                         SMEM_G);

    gemm_h_w<<<dim3(64,4),256,SMEM_PIPE4>>>(h, W);
    gat_attn_proj<<<(Bc*Hh*Nn)/8,256>>>(a_src, a_dst);
    gat_stats<<<Bc*256,256>>>(adj);
    gat_fused<<<512+1024,128,SMEM_G>>>(out, alpha_buf);
}